// round 15
// baseline (speedup 1.0000x reference)
#include <cuda_runtime.h>
#include <cstdint>
#include <cstddef>

// Problem constants
#define BB 256
#define SS 16
#define HH 8
#define HSZ 128
#define DD 1024
#define MM 1024
#define ROWS_L (BB*SS)               // 4096
#define N_ELEM ((size_t)ROWS_L*MM)   // 4,194,304

// ---------------- scratch ----------------
__device__ float g_dense[BB*MM];
__device__ float g_xf[BB*MM];
__device__ float g_xi[BB*MM];
__device__ float g_xo[BB*MM];
__device__ float g_mp[ROWS_L*MM];
__device__ float g_gf[ROWS_L*MM];
__device__ float g_gi[ROWS_L*MM];
__device__ float g_go[ROWS_L*MM];
__device__ float g_wT[8][MM*MM];     // transposed weights [N][K]

struct MegaJobs {                    // 7 independent GEMMs, all K=1024, N=1024
    const float* A[7];
    const float* BT[7];
    const float* bias[7];
    float*       C[7];
};
struct FusedJob {                    // mp2 GEMM + final gating fused
    const float* A;      // mp
    const float* BT;     // W_g^T
    const float* bg;     // b_g
    const float* mp;     // residual (== A)
    const float* m;      // m_state
    const float* gf; const float* gi; const float* go;
    const float* xf; const float* xi; const float* xo;
    float*       out;    // [2, ROWS_L, MM]
};
struct TPtrs { const float* src[8]; float* dst[8]; };

__device__ __forceinline__ uint32_t smem_u32(const void* p) {
    return (uint32_t)__cvta_generic_to_shared(p);
}
__device__ __forceinline__ void cp16(uint32_t dst, const void* src) {
    asm volatile("cp.async.cg.shared.global [%0], [%1], 16;" :: "r"(dst), "l"(src));
}
__device__ __forceinline__ void cp_commit() {
    asm volatile("cp.async.commit_group;" ::: "memory");
}
template <int N>
__device__ __forceinline__ void cp_wait() {
    asm volatile("cp.async.wait_group %0;" :: "n"(N) : "memory");
}
__device__ __forceinline__ void ldsm4(uint32_t& r0, uint32_t& r1,
                                      uint32_t& r2, uint32_t& r3, uint32_t addr) {
    asm volatile("ldmatrix.sync.aligned.m8n8.x4.shared.b16 {%0,%1,%2,%3}, [%4];"
                 : "=r"(r0), "=r"(r1), "=r"(r2), "=r"(r3) : "r"(addr));
}
__device__ __forceinline__ void mma_tf32(
    float& d0, float& d1, float& d2, float& d3,
    uint32_t a0, uint32_t a1, uint32_t a2, uint32_t a3,
    uint32_t b0, uint32_t b1)
{
    asm volatile(
        "mma.sync.aligned.m16n8k8.row.col.f32.tf32.tf32.f32 "
        "{%0,%1,%2,%3}, {%4,%5,%6,%7}, {%8,%9}, {%0,%1,%2,%3};\n"
        : "+f"(d0), "+f"(d1), "+f"(d2), "+f"(d3)
        : "r"(a0), "r"(a1), "r"(a2), "r"(a3), "r"(b0), "r"(b1));
}
__device__ __forceinline__ float sigm(float x) { return 1.f / (1.f + expf(-x)); }

// ---------------- weight transpose (8 matrices 1024x1024) ----------------
__global__ void __launch_bounds__(256) transpose_k(TPtrs tp)
{
    __shared__ float tile[32][33];
    const float* __restrict__ in = tp.src[blockIdx.z];
    float* __restrict__ out      = tp.dst[blockIdx.z];
    const int tx = threadIdx.x, ty = threadIdx.y;   // block (32, 8)
    const int x = blockIdx.x * 32 + tx;
    const int y0 = blockIdx.y * 32 + ty;
#pragma unroll
    for (int j = 0; j < 32; j += 8)
        tile[ty + j][tx] = in[(size_t)(y0 + j) * MM + x];
    __syncthreads();
    const int x2 = blockIdx.y * 32 + tx;
    const int y2 = blockIdx.x * 32 + ty;
#pragma unroll
    for (int j = 0; j < 32; j += 8)
        out[(size_t)(y2 + j) * MM + x2] = tile[tx][ty + j];
}

// ---------------- TF32 GEMM mainloop: cp.async 3-stage, SW128, ldmatrix ---
#define BKT 32
#define TILE_B 16384
#define STAGE_B (2 * TILE_B)
#define NSTAGE 3
#define GEMM_SMEM (NSTAGE * STAGE_B)  // 96 KB

__device__ __forceinline__ void stage_tile(
    const float* __restrict__ Ablk, const float* __restrict__ Bblk,
    int K, int k0, uint32_t bufA, uint32_t bufB, int tid)
{
#pragma unroll
    for (int i = 0; i < 4; i++) {
        const int c = tid + 256 * i;
        const int row = c >> 3, q = c & 7;
        const uint32_t off = row * 128 + ((q * 16) ^ ((row & 7) << 4));
        cp16(bufA + off, Ablk + (size_t)row * K + k0 + q * 4);
        cp16(bufB + off, Bblk + (size_t)row * K + k0 + q * 4);
    }
}

// Fills acc[2][8][4] for the 128x128 tile at (bx, by). Caller owns epilogue.
__device__ __forceinline__ void gemm_mainloop(
    const float* __restrict__ A, const float* __restrict__ BT,
    int K, int bx, int by, char* dynsm, float acc[2][8][4])
{
    const uint32_t sm0 = smem_u32(dynsm);
    const int tid = threadIdx.x, warp = tid >> 5, lane = tid & 31;
    const int warpM = (warp >> 1) * 32;
    const int warpN = (warp & 1) * 64;

    const float* __restrict__ Ablk = A + (size_t)by * 128 * K;
    const float* __restrict__ Bblk = BT + (size_t)bx * 128 * K;

    uint32_t aBase[2], aKey[2];
    {
        const uint32_t r = (lane & 7) + ((lane >> 3) & 1) * 8;
        const uint32_t cb = (lane >> 4) * 16;
#pragma unroll
        for (int mf = 0; mf < 2; mf++) {
            const uint32_t row = warpM + mf * 16 + r;
            aBase[mf] = row * 128;
            aKey[mf]  = ((row & 7) << 4) ^ cb;
        }
    }
    uint32_t bBase[4], bKey[4];
    {
        const uint32_t r = (lane & 7) + ((lane >> 4) & 1) * 8;
        const uint32_t cb = ((lane >> 3) & 1) * 16;
#pragma unroll
        for (int p = 0; p < 4; p++) {
            const uint32_t row = warpN + p * 16 + r;
            bBase[p] = row * 128;
            bKey[p]  = ((row & 7) << 4) ^ cb;
        }
    }

#pragma unroll
    for (int i = 0; i < 2; i++)
#pragma unroll
        for (int j = 0; j < 8; j++)
#pragma unroll
            for (int q = 0; q < 4; q++) acc[i][j][q] = 0.f;

    const int nt = K / BKT;

    stage_tile(Ablk, Bblk, K, 0, sm0, sm0 + TILE_B, tid);
    cp_commit();
    stage_tile(Ablk, Bblk, K, BKT, sm0 + STAGE_B, sm0 + STAGE_B + TILE_B, tid);
    cp_commit();

    for (int t = 0; t < nt; t++) {
        cp_wait<1>();
        __syncthreads();   // single barrier: also orders compute(t-1) before
                           // staging into slot (t+2)%3 == (t-1)%3

        if (t + 2 < nt) {
            const uint32_t sb = sm0 + ((t + 2) % NSTAGE) * STAGE_B;
            stage_tile(Ablk, Bblk, K, (t + 2) * BKT, sb, sb + TILE_B, tid);
        }
        cp_commit();

        const uint32_t abuf = sm0 + (t % NSTAGE) * STAGE_B;
        const uint32_t bbuf = abuf + TILE_B;

#pragma unroll
        for (int ks = 0; ks < BKT; ks += 8) {
            const uint32_t boff = ks * 4;
            uint32_t afr[2][4], bfr[8][2];
#pragma unroll
            for (int mf = 0; mf < 2; mf++)
                ldsm4(afr[mf][0], afr[mf][1], afr[mf][2], afr[mf][3],
                      abuf + aBase[mf] + (boff ^ aKey[mf]));
#pragma unroll
            for (int p = 0; p < 4; p++)
                ldsm4(bfr[2*p][0], bfr[2*p][1], bfr[2*p+1][0], bfr[2*p+1][1],
                      bbuf + bBase[p] + (boff ^ bKey[p]));
#pragma unroll
            for (int mf = 0; mf < 2; mf++)
#pragma unroll
                for (int nf = 0; nf < 8; nf++)
                    mma_tf32(acc[mf][nf][0], acc[mf][nf][1],
                             acc[mf][nf][2], acc[mf][nf][3],
                             afr[mf][0], afr[mf][1], afr[mf][2], afr[mf][3],
                             bfr[nf][0], bfr[nf][1]);
        }
    }
}

// Mega launch: 7 independent GEMMs. Blocks 0..63: jobs 0-3 (proj, 16 CTAs
// each: 8x * 2y). Blocks 64..831: jobs 4-6 (gates, 256 CTAs each: 8x * 32y).
__global__ void __launch_bounds__(256, 2) mega_gemm(MegaJobs jobs)
{
    extern __shared__ char dynsm[];
    const int id = blockIdx.x;
    int job, bx, by;
    if (id < 64) {
        job = id >> 4;
        const int rem = id & 15;
        bx = rem & 7; by = rem >> 3;
    } else {
        const int t2 = id - 64;
        job = 4 + (t2 >> 8);
        const int rem = t2 & 255;
        bx = rem & 7; by = rem >> 3;
    }
    float acc[2][8][4];
    gemm_mainloop(jobs.A[job], jobs.BT[job], MM, bx, by, dynsm, acc);

    const float* __restrict__ bias = jobs.bias[job];
    float* __restrict__ C          = jobs.C[job];
    const int warp = threadIdx.x >> 5, lane = threadIdx.x & 31;
    const int tig = lane & 3, gid = lane >> 2;
    const int row0 = by * 128 + (warp >> 1) * 32;
    const int col0 = bx * 128 + (warp & 1) * 64;
#pragma unroll
    for (int mf = 0; mf < 2; mf++) {
#pragma unroll
        for (int nf = 0; nf < 8; nf++) {
            const int c = col0 + nf * 8 + 2 * tig;
            float bv0 = 0.f, bv1 = 0.f;
            if (bias) { bv0 = bias[c]; bv1 = bias[c + 1]; }
#pragma unroll
            for (int half = 0; half < 2; half++) {
                const int r = row0 + mf * 16 + gid + half * 8;
                float2 out = { acc[mf][nf][half * 2 + 0] + bv0,
                               acc[mf][nf][half * 2 + 1] + bv1 };
                *(float2*)(C + (size_t)r * MM + c) = out;
            }
        }
    }
}

// mp2 GEMM fused with the full final gating: writes d_out directly.
__global__ void __launch_bounds__(256, 2) mp2_final_gemm(FusedJob job)
{
    extern __shared__ char dynsm[];
    float acc[2][8][4];
    gemm_mainloop(job.A, job.BT, MM, blockIdx.x, blockIdx.y, dynsm, acc);

    const int warp = threadIdx.x >> 5, lane = threadIdx.x & 31;
    const int tig = lane & 3, gid = lane >> 2;
    const int row0 = blockIdx.y * 128 + (warp >> 1) * 32;
    const int col0 = blockIdx.x * 128 + (warp & 1) * 64;

#pragma unroll
    for (int mf = 0; mf < 2; mf++) {
#pragma unroll
        for (int nf = 0; nf < 8; nf++) {
            const int c = col0 + nf * 8 + 2 * tig;
            const float bg0 = job.bg[c], bg1 = job.bg[c + 1];
#pragma unroll
            for (int half = 0; half < 2; half++) {
                const int r = row0 + mf * 16 + gid + half * 8;
                const size_t idx  = (size_t)r * MM + c;
                const size_t xidx = (size_t)(r >> 4) * MM + c;

                const float2 mpv = *(const float2*)(job.mp + idx);
                const float2 mv  = *(const float2*)(job.m  + idx);
                const float2 f2  = *(const float2*)(job.gf + idx);
                const float2 i2  = *(const float2*)(job.gi + idx);
                const float2 o2  = *(const float2*)(job.go + idx);
                const float2 fx  = *(const float2*)(job.xf + xidx);
                const float2 ix  = *(const float2*)(job.xi + xidx);
                const float2 ox  = *(const float2*)(job.xo + xidx);

                // mp2 value (GEMM + bias + residual)
                const float p0 = acc[mf][nf][half * 2 + 0] + bg0 + mpv.x;
                const float p1 = acc[mf][nf][half * 2 + 1] + bg1 + mpv.y;

                float2 nm, nh;
                nm.x = sigm(mv.x * sigm(f2.x + fx.x) + 1.f)
                     + p0 * sigm(sigm(i2.x + ix.x));
                nm.y = sigm(mv.y * sigm(f2.y + fx.y) + 1.f)
                     + p1 * sigm(sigm(i2.y + ix.y));
                nh.x = tanhf(mv.x) * sigm(sigm(o2.x + ox.x));
                nh.y = tanhf(mv.y) * sigm(sigm(o2.y + ox.y));

                *(float2*)(job.out + idx) = nm;
                *(float2*)(job.out + N_ELEM + idx) = nh;
            }
        }
    }
}

// ---------------- attention kernel ----------------
__global__ void __launch_bounds__(256) attn_kernel(
    const float* __restrict__ m_state, float* __restrict__ mp_out)
{
    const int bh = blockIdx.x;
    const int b = bh >> 3;
    const int h = bh & 7;
    const int tid = threadIdx.x;

    __shared__ float kv[17][128];
    __shared__ float sc[16][18];

    const float* mbase = m_state + (size_t)b * SS * MM + h * HSZ;
    for (int idx = tid; idx < 16 * 128; idx += 256) {
        int j = idx >> 7, d = idx & 127;
        kv[j][d] = mbase[(size_t)j * MM + d];
    }
    if (tid < 128) kv[16][tid] = g_dense[(size_t)b * MM + h * HSZ + tid];
    __syncthreads();

    const int warp = tid >> 5, lane = tid & 31;
    for (int s = warp; s < 16 * 17; s += 8) {
        const int i = s / 17, j = s % 17;
        float sum = 0.f;
#pragma unroll
        for (int t = 0; t < 4; t++)
            sum += kv[i][lane + t * 32] * kv[j][lane + t * 32];
#pragma unroll
        for (int off = 16; off; off >>= 1)
            sum += __shfl_xor_sync(0xffffffff, sum, off);
        if (lane == 0) sc[i][j] = sum * 0.08838834764831845f;
    }
    __syncthreads();

    if (tid < 16) {
        float mx = -1e30f;
#pragma unroll
        for (int j = 0; j < 17; j++) mx = fmaxf(mx, sc[tid][j]);
        float sum = 0.f;
#pragma unroll
        for (int j = 0; j < 17; j++) {
            float e = expf(sc[tid][j] - mx);
            sc[tid][j] = e;
            sum += e;
        }
        const float inv = 1.f / sum;
#pragma unroll
        for (int j = 0; j < 17; j++) sc[tid][j] *= inv;
    }
    __syncthreads();

    for (int idx = tid; idx < 16 * 128; idx += 256) {
        const int i = idx >> 7, d = idx & 127;
        float a = 0.f;
#pragma unroll
        for (int j = 0; j < 17; j++) a += sc[i][j] * kv[j][d];
        mp_out[((size_t)b * SS + i) * MM + h * HSZ + d] = kv[i][d] + a;
    }
}

// ---------------- launch ----------------
extern "C" void kernel_launch(void* const* d_in, const int* in_sizes, int n_in,
                              void* d_out, int out_size)
{
    const float* inputs  = (const float*)d_in[0];
    const float* h_state = (const float*)d_in[1];
    const float* m_state = (const float*)d_in[2];
    const float* W_emb   = (const float*)d_in[3];
    const float* b_emb   = (const float*)d_in[4];
    const float* W_g     = (const float*)d_in[5];
    const float* b_g     = (const float*)d_in[6];
    const float* W_wf    = (const float*)d_in[7];
    const float* W_wi    = (const float*)d_in[8];
    const float* W_wo    = (const float*)d_in[9];
    const float* W_uf    = (const float*)d_in[10];
    const float* b_uf    = (const float*)d_in[11];
    const float* W_ui    = (const float*)d_in[12];
    const float* b_ui    = (const float*)d_in[13];
    const float* W_uo    = (const float*)d_in[14];
    const float* b_uo    = (const float*)d_in[15];

    float *p_dense, *p_xf, *p_xi, *p_xo, *p_mp, *p_gf, *p_gi, *p_go, *p_wT;
    cudaGetSymbolAddress((void**)&p_dense, g_dense);
    cudaGetSymbolAddress((void**)&p_xf, g_xf);
    cudaGetSymbolAddress((void**)&p_xi, g_xi);
    cudaGetSymbolAddress((void**)&p_xo, g_xo);
    cudaGetSymbolAddress((void**)&p_mp, g_mp);
    cudaGetSymbolAddress((void**)&p_gf, g_gf);
    cudaGetSymbolAddress((void**)&p_gi, g_gi);
    cudaGetSymbolAddress((void**)&p_go, g_go);
    cudaGetSymbolAddress((void**)&p_wT, g_wT);

    float* wt[8];
    for (int i = 0; i < 8; i++) wt[i] = p_wT + (size_t)i * MM * MM;

    cudaFuncSetAttribute(mega_gemm, cudaFuncAttributeMaxDynamicSharedMemorySize, GEMM_SMEM);
    cudaFuncSetAttribute(mp2_final_gemm, cudaFuncAttributeMaxDynamicSharedMemorySize, GEMM_SMEM);

    // 0) transpose all 8 weight matrices: order emb, wf, wi, wo, uf, ui, uo, g
    {
        TPtrs tp;
        tp.src[0] = W_emb; tp.src[1] = W_wf; tp.src[2] = W_wi; tp.src[3] = W_wo;
        tp.src[4] = W_uf;  tp.src[5] = W_ui; tp.src[6] = W_uo; tp.src[7] = W_g;
        for (int i = 0; i < 8; i++) tp.dst[i] = wt[i];
        transpose_k<<<dim3(32, 32, 8), dim3(32, 8)>>>(tp);
    }

    // 1) ALL 7 independent GEMMs in one launch:
    //    jobs 0-3: dense/xf/xi/xo (A=inputs, 16 CTAs each)
    //    jobs 4-6: gate pre-activations WITHOUT x-term (A=h_state, 256 each)
    {
        MegaJobs mj;
        mj.A[0] = inputs;  mj.BT[0] = wt[0]; mj.bias[0] = b_emb;   mj.C[0] = p_dense;
        mj.A[1] = inputs;  mj.BT[1] = wt[1]; mj.bias[1] = nullptr; mj.C[1] = p_xf;
        mj.A[2] = inputs;  mj.BT[2] = wt[2]; mj.bias[2] = nullptr; mj.C[2] = p_xi;
        mj.A[3] = inputs;  mj.BT[3] = wt[3]; mj.bias[3] = nullptr; mj.C[3] = p_xo;
        mj.A[4] = h_state; mj.BT[4] = wt[4]; mj.bias[4] = b_uf;    mj.C[4] = p_gf;
        mj.A[5] = h_state; mj.BT[5] = wt[5]; mj.bias[5] = b_ui;    mj.C[5] = p_gi;
        mj.A[6] = h_state; mj.BT[6] = wt[6]; mj.bias[6] = b_uo;    mj.C[6] = p_go;
        mega_gemm<<<832, 256, GEMM_SMEM>>>(mj);
    }

    // 2) attention -> memory proposal (needs g_dense)
    attn_kernel<<<BB * HH, 256>>>(m_state, p_mp);

    // 3) mp2 GEMM + final gating fused, writes d_out directly
    {
        FusedJob fj;
        fj.A = p_mp; fj.BT = wt[7]; fj.bg = b_g; fj.mp = p_mp;
        fj.m = m_state;
        fj.gf = p_gf; fj.gi = p_gi; fj.go = p_go;
        fj.xf = p_xf; fj.xi = p_xi; fj.xo = p_xo;
        fj.out = (float*)d_out;
        mp2_final_gemm<<<dim3(MM/128, ROWS_L/128), 256, GEMM_SMEM>>>(fj);
    }
}